// round 15
// baseline (speedup 1.0000x reference)
#include <cuda_runtime.h>
#include <cuda_fp16.h>
#include <cstddef>
#include <cstdint>

#define F 128
#define MAXN 40000
#define MAXE 640000

// Scratch (no cudaMalloc allowed): __device__ globals.
__device__ float    g_pd[(size_t)MAXN * F];    // proj_dst + b1 (fp32)
__device__ uint32_t g_nt[(size_t)MAXN * F];    // neigh (tf32/fp32 bits, edge out)
__device__ uint4    g_pf[(size_t)MAXN * 32];   // packed fp16: per node 32 x 16B
                                               //  group g: [ps h(4g..4g+3) | feat h(4g..4g+3)]
__device__ uint32_t g_w1t[2 * F * F];          // w1 tf32 (RNA)
__device__ uint32_t g_wft[2 * F * F];          // wf tf32 (RNA)
__device__ int      g_rp[MAXN + 1];            // CSR row ptr over sorted dst

// ---------------------------------------------------------------------------
// helpers
// ---------------------------------------------------------------------------
__device__ __forceinline__ uint32_t f2tf(float x) {
    uint32_t r;
    asm("cvt.rna.tf32.f32 %0, %1;" : "=r"(r) : "f"(x));
    return r;
}
__device__ __forceinline__ void mma_tf32(float* c,
    uint32_t a0, uint32_t a1, uint32_t a2, uint32_t a3,
    uint32_t b0, uint32_t b1)
{
    asm("mma.sync.aligned.m16n8k8.row.col.f32.tf32.tf32.f32 "
        "{%0,%1,%2,%3}, {%4,%5,%6,%7}, {%8,%9}, {%0,%1,%2,%3};"
        : "+f"(c[0]), "+f"(c[1]), "+f"(c[2]), "+f"(c[3])
        : "r"(a0), "r"(a1), "r"(a2), "r"(a3), "r"(b0), "r"(b1));
}
__device__ __forceinline__ float tanh_fast(float x) {
    float r;
    asm("tanh.approx.f32 %0, %1;" : "=f"(r) : "f"(x));
    return r;
}
__device__ __forceinline__ float2 unp_h2(uint32_t u) {
    __half2 h = *reinterpret_cast<__half2*>(&u);
    return __half22float2(h);
}
#define CP16(dst, src) \
    asm volatile("cp.async.cg.shared.global [%0], [%1], 16;" :: "r"(dst), "l"(src))
#define CP_COMMIT() asm volatile("cp.async.commit_group;" ::: "memory")
#define CP_WAIT2()  asm volatile("cp.async.wait_group 2;" ::: "memory")

// ---------------------------------------------------------------------------
// conv_pf: feat fp32 -> fp16 halves into g_pf feat slots (GEMM A needs no
// conversion: raw fp32 bits are valid truncated-tf32 operands).
// ---------------------------------------------------------------------------
__global__ void conv_pf(const float* __restrict__ x, int n4)
{
    int i = blockIdx.x * blockDim.x + threadIdx.x;
    if (i >= n4) return;
    float4 v = ((const float4*)x)[i];
    __half2 h01 = __floats2half2_rn(v.x, v.y);
    __half2 h23 = __floats2half2_rn(v.z, v.w);
    uint2 pk = {*(uint32_t*)&h01, *(uint32_t*)&h23};
    uint8_t* pf = (uint8_t*)g_pf;
    size_t off = ((size_t)(i >> 5) * 32 + (i & 31)) * 16 + 8;   // feat slot
    *(uint2*)(pf + off) = pk;
}

// both weight matrices fp32 -> tf32 (RNA) in one launch
__global__ void conv_w(const float* __restrict__ w1, const float* __restrict__ wf)
{
    int i = blockIdx.x * blockDim.x + threadIdx.x;   // 0..16383
    const int half_n = 2 * F * F / 4;                // 8192
    const float* src = (i < half_n) ? w1 : wf;
    uint32_t* dst    = (i < half_n) ? g_w1t : g_wft;
    int j = (i < half_n) ? i : i - half_n;
    float4 v = ((const float4*)src)[j];
    uint4 o = {f2tf(v.x), f2tf(v.y), f2tf(v.z), f2tf(v.w)};
    ((uint4*)dst)[j] = o;
}

// ---------------------------------------------------------------------------
// Shared tile geometry
// ---------------------------------------------------------------------------
#define A_STW 20
#define B_STW 136
#define A_STAGE_W (128 * A_STW)          // 2560 words
#define B_STAGE_W (16 * B_STW)           // 2176 words
#define NSTAGE 4

// ---------------------------------------------------------------------------
// gemm_pair: ONE 512-thread CTA computes BOTH projections sharing A.
//   warps 0-7  : pd = A @ B0 + bias  (fp32)
//   warps 8-15 : ps = A @ B1 -> packed fp16 into g_pf ps slots
// A raw fp32-as-tf32, staged once/stage; B0+B1 both staged. 4-stage cp.async,
// wait_group 2, empty tail commits. Per stage: 64 MMAs vs one wait+sync.
// smem 110.6 KB -> 1 CTA/SM (16 warps, same resident warps as 2x256 config).
// ---------------------------------------------------------------------------
#define PAIR_SMEM ((NSTAGE * (A_STAGE_W + 2 * B_STAGE_W)) * 4)   // 110592 B

__global__ void __launch_bounds__(512) gemm_pair(
    const uint32_t* __restrict__ A,
    const uint32_t* __restrict__ B0, const uint32_t* __restrict__ B1,
    const float* __restrict__ bias0, float* __restrict__ C0, int M)
{
    extern __shared__ uint32_t smw[];
    uint32_t* sA  = smw;
    uint32_t* sB0 = smw + NSTAGE * A_STAGE_W;
    uint32_t* sB1 = sB0 + NSTAGE * B_STAGE_W;

    const int tid  = threadIdx.x;
    const int lane = tid & 31;
    const int warp = tid >> 5;          // 0..15
    const int out  = warp >> 3;         // 0: pd, 1: ps-pack
    const int wl   = warp & 7;
    const int g    = lane >> 2;
    const int tg   = lane & 3;
    const int m0   = blockIdx.x * 128;
    const int wr   = (wl & 3) * 32;
    const int wc   = (wl >> 2) * 64;

    // staging: 1 A chunk + 1 B0 chunk + 1 B1 chunk per thread
    const int a_row = tid >> 2;              // 0..127
    const int a_kc  = (tid & 3) * 4;
    const int b_row = tid >> 5;              // 0..15
    const int b_nc  = (tid & 31) * 4;
    const int ar    = min(m0 + a_row, M - 1);

    const uint32_t sA_b  = (uint32_t)__cvta_generic_to_shared(sA);
    const uint32_t sB0_b = (uint32_t)__cvta_generic_to_shared(sB0);
    const uint32_t sB1_b = (uint32_t)__cvta_generic_to_shared(sB1);

    auto issue_stage = [&](int st) {
        if (st < 8) {
            const int buf = st & (NSTAGE - 1);
            const int k0 = st * 16;
            CP16(sA_b + (buf * A_STAGE_W + a_row * A_STW + a_kc) * 4,
                 A + (size_t)ar * 128 + k0 + a_kc);
            CP16(sB0_b + (buf * B_STAGE_W + b_row * B_STW + b_nc) * 4,
                 B0 + (size_t)(k0 + b_row) * 128 + b_nc);
            CP16(sB1_b + (buf * B_STAGE_W + b_row * B_STW + b_nc) * 4,
                 B1 + (size_t)(k0 + b_row) * 128 + b_nc);
        }
        CP_COMMIT();
    };

    float acc[2][8][4];
#pragma unroll
    for (int mt = 0; mt < 2; mt++)
#pragma unroll
        for (int j = 0; j < 8; j++)
#pragma unroll
            for (int i = 0; i < 4; i++) acc[mt][j][i] = 0.f;

    issue_stage(0);
    issue_stage(1);
    issue_stage(2);

    const uint32_t* sBme = out ? sB1 : sB0;

    for (int st = 0; st < 8; st++) {
        const int buf = st & (NSTAGE - 1);
        CP_WAIT2();
        __syncthreads();
        issue_stage(st + 3);

        const uint32_t* Ab = sA + buf * A_STAGE_W;
        const uint32_t* Bb = sBme + buf * B_STAGE_W;
#pragma unroll
        for (int kk = 0; kk < 16; kk += 8) {
            uint32_t a[2][4];
#pragma unroll
            for (int mt = 0; mt < 2; mt++) {
                const uint32_t* r0 = Ab + (wr + mt * 16 + g) * A_STW + kk + tg;
                const uint32_t* r1 = r0 + 8 * A_STW;
                a[mt][0] = r0[0];
                a[mt][1] = r1[0];
                a[mt][2] = r0[4];
                a[mt][3] = r1[4];
            }
#pragma unroll
            for (int j = 0; j < 8; j++) {
                uint32_t b0 = Bb[(kk + tg) * B_STW + wc + 8 * j + g];
                uint32_t b1 = Bb[(kk + tg + 4) * B_STW + wc + 8 * j + g];
                mma_tf32(acc[0][j], a[0][0], a[0][1], a[0][2], a[0][3], b0, b1);
                mma_tf32(acc[1][j], a[1][0], a[1][1], a[1][2], a[1][3], b0, b1);
            }
        }
    }

    // epilogue
    uint8_t* pf = (uint8_t*)g_pf;
#pragma unroll
    for (int mt = 0; mt < 2; mt++) {
#pragma unroll
        for (int j = 0; j < 8; j++) {
            int col = wc + 8 * j + 2 * tg;
            int r0 = m0 + wr + 16 * mt + g;
            int r1 = r0 + 8;
            if (out) {   // packed fp16 ps slots
                size_t o0 = (size_t)r0 * 512 + (col >> 2) * 16 + (col & 3) * 2;
                size_t o1 = (size_t)r1 * 512 + (col >> 2) * 16 + (col & 3) * 2;
                if (r0 < M)
                    *(__half2*)(pf + o0) = __floats2half2_rn(acc[mt][j][0], acc[mt][j][1]);
                if (r1 < M)
                    *(__half2*)(pf + o1) = __floats2half2_rn(acc[mt][j][2], acc[mt][j][3]);
            } else {
                float bv0 = bias0[col];
                float bv1 = bias0[col + 1];
                if (r0 < M) {
                    float2 v = {acc[mt][j][0] + bv0, acc[mt][j][1] + bv1};
                    *(float2*)(C0 + (size_t)r0 * 128 + col) = v;
                }
                if (r1 < M) {
                    float2 v = {acc[mt][j][2] + bv0, acc[mt][j][3] + bv1};
                    *(float2*)(C0 + (size_t)r1 * 128 + col) = v;
                }
            }
        }
    }
}

// ---------------------------------------------------------------------------
// tf32 GEMM (dual-source), 4-stage cp.async pipeline — final output GEMM.
//   C = A1 @ B1a + A2 @ B2 + bias. A raw fp32-as-tf32 / tf32 bits.
// ---------------------------------------------------------------------------
#define GEMM_SMEM ((NSTAGE * A_STAGE_W + NSTAGE * B_STAGE_W) * 4)  // 75776 B

__global__ void __launch_bounds__(256) gemm_tf32(
    const uint32_t* __restrict__ A1, const uint32_t* __restrict__ B1a,
    const uint32_t* __restrict__ A2, const uint32_t* __restrict__ B2,
    const float* __restrict__ bias_a, float* __restrict__ Ca, int M)
{
    extern __shared__ uint32_t smw[];
    uint32_t* sA = smw;
    uint32_t* sB = smw + NSTAGE * A_STAGE_W;

    const int tid  = threadIdx.x;
    const int lane = tid & 31;
    const int warp = tid >> 5;
    const int g    = lane >> 2;
    const int tg   = lane & 3;
    const int m0   = blockIdx.x * 128;
    const int wr   = (warp & 3) * 32;
    const int wc   = (warp >> 2) * 64;

    const int nst = A2 ? 16 : 8;

    const int a_row0 = tid >> 2;
    const int a_kc   = (tid & 3) * 4;
    const int b_row0 = tid >> 5;
    const int b_nc   = (tid & 31) * 4;
    const int ar0 = min(m0 + a_row0,      M - 1);
    const int ar1 = min(m0 + a_row0 + 64, M - 1);

    const uint32_t sA_b = (uint32_t)__cvta_generic_to_shared(sA);
    const uint32_t sB_b = (uint32_t)__cvta_generic_to_shared(sB);

    auto issue_stage = [&](int st) {
        if (st < nst) {
            const int buf = st & (NSTAGE - 1);
            const uint32_t* A = (st >= 8) ? A2 : A1;
            const uint32_t* B = (st >= 8) ? B2 : B1a;
            const int k0 = (st & 7) * 16;
            CP16(sA_b + (buf * A_STAGE_W + a_row0 * A_STW + a_kc) * 4,
                 A + (size_t)ar0 * 128 + k0 + a_kc);
            CP16(sA_b + (buf * A_STAGE_W + (a_row0 + 64) * A_STW + a_kc) * 4,
                 A + (size_t)ar1 * 128 + k0 + a_kc);
            CP16(sB_b + (buf * B_STAGE_W + b_row0 * B_STW + b_nc) * 4,
                 B + (size_t)(k0 + b_row0) * 128 + b_nc);
            CP16(sB_b + (buf * B_STAGE_W + (b_row0 + 8) * B_STW + b_nc) * 4,
                 B + (size_t)(k0 + b_row0 + 8) * 128 + b_nc);
        }
        CP_COMMIT();
    };

    float acc[2][8][4];
#pragma unroll
    for (int mt = 0; mt < 2; mt++)
#pragma unroll
        for (int j = 0; j < 8; j++)
#pragma unroll
            for (int i = 0; i < 4; i++) acc[mt][j][i] = 0.f;

    issue_stage(0);
    issue_stage(1);
    issue_stage(2);

    for (int st = 0; st < nst; st++) {
        const int buf = st & (NSTAGE - 1);
        CP_WAIT2();
        __syncthreads();
        issue_stage(st + 3);

        const uint32_t* Ab = sA + buf * A_STAGE_W;
        const uint32_t* Bb = sB + buf * B_STAGE_W;
#pragma unroll
        for (int kk = 0; kk < 16; kk += 8) {
            uint32_t a[2][4];
#pragma unroll
            for (int mt = 0; mt < 2; mt++) {
                const uint32_t* r0 = Ab + (wr + mt * 16 + g) * A_STW + kk + tg;
                const uint32_t* r1 = r0 + 8 * A_STW;
                a[mt][0] = r0[0];
                a[mt][1] = r1[0];
                a[mt][2] = r0[4];
                a[mt][3] = r1[4];
            }
#pragma unroll
            for (int j = 0; j < 8; j++) {
                uint32_t b0 = Bb[(kk + tg) * B_STW + wc + 8 * j + g];
                uint32_t b1 = Bb[(kk + tg + 4) * B_STW + wc + 8 * j + g];
                mma_tf32(acc[0][j], a[0][0], a[0][1], a[0][2], a[0][3], b0, b1);
                mma_tf32(acc[1][j], a[1][0], a[1][1], a[1][2], a[1][3], b0, b1);
            }
        }
    }

#pragma unroll
    for (int mt = 0; mt < 2; mt++) {
#pragma unroll
        for (int j = 0; j < 8; j++) {
            int col = wc + 8 * j + 2 * tg;
            float bv0 = bias_a ? bias_a[col]     : 0.f;
            float bv1 = bias_a ? bias_a[col + 1] : 0.f;
            int r0 = m0 + wr + 16 * mt + g;
            if (r0 < M) {
                float2 v = {acc[mt][j][0] + bv0, acc[mt][j][1] + bv1};
                *(float2*)(Ca + (size_t)r0 * 128 + col) = v;
            }
            int r1 = r0 + 8;
            if (r1 < M) {
                float2 v = {acc[mt][j][2] + bv0, acc[mt][j][3] + bv1};
                *(float2*)(Ca + (size_t)r1 * 128 + col) = v;
            }
        }
    }
}

// ---------------------------------------------------------------------------
// rowptr by scatter: thread per edge; writes rp[n]=e for n in (dst[e-1],dst[e]].
// ---------------------------------------------------------------------------
__global__ void rowptr_kernel(const int* __restrict__ dst, int N, int E)
{
    int e = blockIdx.x * blockDim.x + threadIdx.x;
    if (e >= E) return;
    int d1 = dst[e];
    int d0 = (e == 0) ? -1 : dst[e - 1];
    for (int n = d0 + 1; n <= d1; n++) g_rp[n] = e;
    if (e == E - 1)
        for (int n = d1 + 1; n <= N; n++) g_rp[n] = E;
}

// ---------------------------------------------------------------------------
// Fused edge phase, max-free softmax. One WARP per node; lane owns feats
// 4l..4l+3. ps+feat read as ONE packed fp16 LDG.128 per edge per lane.
// ---------------------------------------------------------------------------
__global__ void __launch_bounds__(256) edge_fused_kernel(
    const int* __restrict__ src, const float* __restrict__ w2, int N)
{
    const int gw   = (blockIdx.x * blockDim.x + threadIdx.x) >> 5;
    const int lane = threadIdx.x & 31;
    if (gw >= N) return;
    const int node = gw;
    const int r0 = g_rp[node], r1 = g_rp[node + 1];

    const float4 pdv = ((const float4*)(g_pd + (size_t)node * F))[lane];
    const float4 wv  = ((const float4*)w2)[lane];

    float4 acc = {0.f, 0.f, 0.f, 0.f};
    float  den = 0.f;

    int e = r0;
    for (; e + 2 <= r1; e += 2) {
        int s0 = __ldg(src + e);
        int s1 = __ldg(src + e + 1);
        uint4 v0 = g_pf[(size_t)s0 * 32 + lane];
        uint4 v1 = g_pf[(size_t)s1 * 32 + lane];
        float2 p0a = unp_h2(v0.x), p0b = unp_h2(v0.y);
        float2 f0a = unp_h2(v0.z), f0b = unp_h2(v0.w);
        float2 p1a = unp_h2(v1.x), p1b = unp_h2(v1.y);
        float2 f1a = unp_h2(v1.z), f1b = unp_h2(v1.w);

        float sc0 = wv.x * tanh_fast(pdv.x + p0a.x) + wv.y * tanh_fast(pdv.y + p0a.y)
                  + wv.z * tanh_fast(pdv.z + p0b.x) + wv.w * tanh_fast(pdv.w + p0b.y);
        float sc1 = wv.x * tanh_fast(pdv.x + p1a.x) + wv.y * tanh_fast(pdv.y + p1a.y)
                  + wv.z * tanh_fast(pdv.z + p1b.x) + wv.w * tanh_fast(pdv.w + p1b.y);
#pragma unroll
        for (int o = 16; o; o >>= 1) {
            sc0 += __shfl_xor_sync(0xffffffffu, sc0, o);
            sc1 += __shfl_xor_sync(0xffffffffu, sc1, o);
        }
        float ex0 = __expf(sc0);
        float ex1 = __expf(sc1);
        den += ex0 + ex1;
        acc.x = fmaf(ex0, f0a.x, acc.x); acc.x = fmaf(ex1, f1a.x, acc.x);
        acc.y = fmaf(ex0, f0a.y, acc.y); acc.y = fmaf(ex1, f1a.y, acc.y);
        acc.z = fmaf(ex0, f0b.x, acc.z); acc.z = fmaf(ex1, f1b.x, acc.z);
        acc.w = fmaf(ex0, f0b.y, acc.w); acc.w = fmaf(ex1, f1b.y, acc.w);
    }
    if (e < r1) {
        int s0 = __ldg(src + e);
        uint4 v0 = g_pf[(size_t)s0 * 32 + lane];
        float2 p0a = unp_h2(v0.x), p0b = unp_h2(v0.y);
        float2 f0a = unp_h2(v0.z), f0b = unp_h2(v0.w);
        float sc0 = wv.x * tanh_fast(pdv.x + p0a.x) + wv.y * tanh_fast(pdv.y + p0a.y)
                  + wv.z * tanh_fast(pdv.z + p0b.x) + wv.w * tanh_fast(pdv.w + p0b.y);
#pragma unroll
        for (int o = 16; o; o >>= 1) sc0 += __shfl_xor_sync(0xffffffffu, sc0, o);
        float ex0 = __expf(sc0);
        den += ex0;
        acc.x = fmaf(ex0, f0a.x, acc.x);
        acc.y = fmaf(ex0, f0a.y, acc.y);
        acc.z = fmaf(ex0, f0b.x, acc.z);
        acc.w = fmaf(ex0, f0b.y, acc.w);
    }

    const float inv = (r1 > r0) ? (1.0f / den) : 0.f;
    uint4 o = {f2tf(acc.x * inv), f2tf(acc.y * inv),
               f2tf(acc.z * inv), f2tf(acc.w * inv)};
    ((uint4*)(g_nt + (size_t)node * F))[lane] = o;
}

// ---------------------------------------------------------------------------
extern "C" void kernel_launch(void* const* d_in, const int* in_sizes, int n_in,
                              void* d_out, int out_size)
{
    const float* feat = (const float*)d_in[0];
    const int*   src  = (const int*)d_in[1];
    const int*   dst  = (const int*)d_in[2];
    const float* w1   = (const float*)d_in[3];
    const float* b1   = (const float*)d_in[4];
    const float* w2   = (const float*)d_in[5];
    // d_in[6] = b2: cancels in softmax, unused
    const float* wf   = (const float*)d_in[7];
    const float* bf   = (const float*)d_in[8];
    float* out = (float*)d_out;

    const int N = in_sizes[0] / F;   // 40000
    const int E = in_sizes[1];       // 640000

    static int init_done = 0;
    static cudaStream_t s_side;
    static cudaEvent_t ev_fork, ev_side;
    if (!init_done) {
        cudaFuncSetAttribute(gemm_tf32,
            cudaFuncAttributeMaxDynamicSharedMemorySize, GEMM_SMEM);
        cudaFuncSetAttribute(gemm_pair,
            cudaFuncAttributeMaxDynamicSharedMemorySize, PAIR_SMEM);
        cudaStreamCreateWithFlags(&s_side, cudaStreamNonBlocking);
        cudaEventCreateWithFlags(&ev_fork, cudaEventDisableTiming);
        cudaEventCreateWithFlags(&ev_side, cudaEventDisableTiming);
        init_done = 1;
    }

    float *pd;
    uint32_t *nt, *w1t, *wft;
    cudaGetSymbolAddress((void**)&pd,  g_pd);
    cudaGetSymbolAddress((void**)&nt,  g_nt);
    cudaGetSymbolAddress((void**)&w1t, g_w1t);
    cudaGetSymbolAddress((void**)&wft, g_wft);

    const uint32_t* fe32 = (const uint32_t*)feat;   // raw fp32 = truncated tf32
    const int gblocks = (N + 127) / 128;            // 313

    // ---- side stream: rowptr + packed-fp16 feat halves (hide under GEMM1) ----
    cudaEventRecord(ev_fork, 0);
    cudaStreamWaitEvent(s_side, ev_fork, 0);
    rowptr_kernel<<<(E + 255) / 256, 256, 0, s_side>>>(dst, N, E);
    conv_pf<<<(N * F / 4 + 255) / 256, 256, 0, s_side>>>(feat, N * F / 4);
    cudaEventRecord(ev_side, s_side);

    // ---- main stream ----
    // 0) weights -> tf32 (tiny, gates GEMM1)
    conv_w<<<(4 * F * F / 4 + 255) / 256, 256>>>(w1, wf);

    // 1) A-shared pair GEMM: pd = feat@w1[:F]+b1 ; ps = feat@w1[F:] -> g_pf
    gemm_pair<<<gblocks, 512, PAIR_SMEM>>>(
        fe32, w1t, w1t + F * F, b1, pd, N);

    // 2) edge phase (needs rowptr + g_pf feat halves from side, pd/ps from GEMM1)
    cudaStreamWaitEvent(0, ev_side, 0);
    edge_fused_kernel<<<(N * 32 + 255) / 256, 256>>>(src, w2, N);

    // 3) out = feat @ wf[:F] + neigh @ wf[F:] + bf  (dual-source GEMM)
    gemm_tf32<<<gblocks, 256, GEMM_SMEM>>>(
        fe32, wft, nt, wft + F * F, bf, out, N);
}

// round 16
// speedup vs baseline: 1.0467x; 1.0467x over previous
#include <cuda_runtime.h>
#include <cuda_fp16.h>
#include <cstddef>
#include <cstdint>

#define F 128
#define MAXN 40000
#define MAXE 640000

// Scratch (no cudaMalloc allowed): __device__ globals.
__device__ float    g_pd[(size_t)MAXN * F];    // proj_dst + b1 (fp32)
__device__ uint32_t g_nt[(size_t)MAXN * F];    // neigh (tf32/fp32 bits, edge out)
__device__ uint4    g_pf[(size_t)MAXN * 32];   // packed fp16: per node 32 x 16B
                                               //  group g: [ps h(4g..4g+3) | feat h(4g..4g+3)]
__device__ int      g_rp[MAXN + 1];            // CSR row ptr over sorted dst

// ---------------------------------------------------------------------------
// helpers
// ---------------------------------------------------------------------------
__device__ __forceinline__ uint32_t f2tf(float x) {
    uint32_t r;
    asm("cvt.rna.tf32.f32 %0, %1;" : "=r"(r) : "f"(x));
    return r;
}
__device__ __forceinline__ void mma_tf32(float* c,
    uint32_t a0, uint32_t a1, uint32_t a2, uint32_t a3,
    uint32_t b0, uint32_t b1)
{
    asm("mma.sync.aligned.m16n8k8.row.col.f32.tf32.tf32.f32 "
        "{%0,%1,%2,%3}, {%4,%5,%6,%7}, {%8,%9}, {%0,%1,%2,%3};"
        : "+f"(c[0]), "+f"(c[1]), "+f"(c[2]), "+f"(c[3])
        : "r"(a0), "r"(a1), "r"(a2), "r"(a3), "r"(b0), "r"(b1));
}
__device__ __forceinline__ float tanh_fast(float x) {
    float r;
    asm("tanh.approx.f32 %0, %1;" : "=f"(r) : "f"(x));
    return r;
}
__device__ __forceinline__ float2 unp_h2(uint32_t u) {
    __half2 h = *reinterpret_cast<__half2*>(&u);
    return __half22float2(h);
}
#define CP16(dst, src) \
    asm volatile("cp.async.cg.shared.global [%0], [%1], 16;" :: "r"(dst), "l"(src))
#define CP_COMMIT() asm volatile("cp.async.commit_group;" ::: "memory")
#define CP_WAIT2()  asm volatile("cp.async.wait_group 2;" ::: "memory")

// ---------------------------------------------------------------------------
// conv_pf: feat fp32 -> fp16 halves into g_pf feat slots. (GEMM A and B need
// no conversion: raw fp32 bits are valid truncated-tf32 operands.)
// ---------------------------------------------------------------------------
__global__ void conv_pf(const float* __restrict__ x, int n4)
{
    int i = blockIdx.x * blockDim.x + threadIdx.x;
    if (i >= n4) return;
    float4 v = ((const float4*)x)[i];
    __half2 h01 = __floats2half2_rn(v.x, v.y);
    __half2 h23 = __floats2half2_rn(v.z, v.w);
    uint2 pk = {*(uint32_t*)&h01, *(uint32_t*)&h23};
    uint8_t* pf = (uint8_t*)g_pf;
    size_t off = ((size_t)(i >> 5) * 32 + (i & 31)) * 16 + 8;   // feat slot
    *(uint2*)(pf + off) = pk;
}

// ---------------------------------------------------------------------------
// tf32 GEMM, 4-stage cp.async pipeline (3 lookahead, wait_group 2, empty tail
// commits keep accounting exact). Grid (blocks_m, ysel).
//   ysel==0: Ca = A1 @ B1a (+ A2 @ B2 if A2) (+ bias_a)   -> fp32 C
//   ysel==1: A1 @ B1b -> packed fp16 into g_pf ps slots
// A and B operands are raw fp32 bits (valid truncated tf32).
// Block tile 128x128, 256 threads, 8 warps 4x2; warp tile m32 x n64; BK=16.
// smem: A [m][k] stride 20, B [k][n] stride 136 — conflict-free.
// launch_bounds(256) [2 CTAs/SM]: measured-best.
// ---------------------------------------------------------------------------
#define A_STW 20
#define B_STW 136
#define A_STAGE_W (128 * A_STW)
#define B_STAGE_W (16 * B_STW)
#define NSTAGE 4
#define GEMM_SMEM ((NSTAGE * A_STAGE_W + NSTAGE * B_STAGE_W) * 4)  // 75776 B

__global__ void __launch_bounds__(256) gemm_tf32(
    const uint32_t* __restrict__ A1,
    const uint32_t* __restrict__ B1a, const uint32_t* __restrict__ B1b,
    const uint32_t* __restrict__ A2,  const uint32_t* __restrict__ B2,
    const float* __restrict__ bias_a,
    float* __restrict__ Ca, int pack_b, int M)
{
    extern __shared__ uint32_t smw[];
    uint32_t* sA = smw;
    uint32_t* sB = smw + NSTAGE * A_STAGE_W;

    const int tid  = threadIdx.x;
    const int lane = tid & 31;
    const int warp = tid >> 5;
    const int g    = lane >> 2;
    const int tg   = lane & 3;
    const int m0   = blockIdx.x * 128;
    const int wr   = (warp & 3) * 32;
    const int wc   = (warp >> 2) * 64;

    const uint32_t* B1 = blockIdx.y ? B1b : B1a;
    const int nst = (blockIdx.y == 0 && A2) ? 16 : 8;

    const int a_row0 = tid >> 2;
    const int a_kc   = (tid & 3) * 4;
    const int b_row0 = tid >> 5;
    const int b_nc   = (tid & 31) * 4;
    const int ar0 = min(m0 + a_row0,      M - 1);
    const int ar1 = min(m0 + a_row0 + 64, M - 1);

    const uint32_t sA_b = (uint32_t)__cvta_generic_to_shared(sA);
    const uint32_t sB_b = (uint32_t)__cvta_generic_to_shared(sB);

    auto issue_stage = [&](int st) {
        if (st < nst) {
            const int buf = st & (NSTAGE - 1);
            const uint32_t* A = (st >= 8) ? A2 : A1;
            const uint32_t* B = (st >= 8) ? B2 : B1;
            const int k0 = (st & 7) * 16;
            CP16(sA_b + (buf * A_STAGE_W + a_row0 * A_STW + a_kc) * 4,
                 A + (size_t)ar0 * 128 + k0 + a_kc);
            CP16(sA_b + (buf * A_STAGE_W + (a_row0 + 64) * A_STW + a_kc) * 4,
                 A + (size_t)ar1 * 128 + k0 + a_kc);
            CP16(sB_b + (buf * B_STAGE_W + b_row0 * B_STW + b_nc) * 4,
                 B + (size_t)(k0 + b_row0) * 128 + b_nc);
            CP16(sB_b + (buf * B_STAGE_W + (b_row0 + 8) * B_STW + b_nc) * 4,
                 B + (size_t)(k0 + b_row0 + 8) * 128 + b_nc);
        }
        CP_COMMIT();
    };

    float acc[2][8][4];
#pragma unroll
    for (int mt = 0; mt < 2; mt++)
#pragma unroll
        for (int j = 0; j < 8; j++)
#pragma unroll
            for (int i = 0; i < 4; i++) acc[mt][j][i] = 0.f;

    issue_stage(0);
    issue_stage(1);
    issue_stage(2);

    for (int st = 0; st < nst; st++) {
        const int buf = st & (NSTAGE - 1);
        CP_WAIT2();
        __syncthreads();
        issue_stage(st + 3);

        const uint32_t* Ab = sA + buf * A_STAGE_W;
        const uint32_t* Bb = sB + buf * B_STAGE_W;
#pragma unroll
        for (int kk = 0; kk < 16; kk += 8) {
            uint32_t a[2][4];
#pragma unroll
            for (int mt = 0; mt < 2; mt++) {
                const uint32_t* r0 = Ab + (wr + mt * 16 + g) * A_STW + kk + tg;
                const uint32_t* r1 = r0 + 8 * A_STW;
                a[mt][0] = r0[0];
                a[mt][1] = r1[0];
                a[mt][2] = r0[4];
                a[mt][3] = r1[4];
            }
#pragma unroll
            for (int j = 0; j < 8; j++) {
                uint32_t b0 = Bb[(kk + tg) * B_STW + wc + 8 * j + g];
                uint32_t b1 = Bb[(kk + tg + 4) * B_STW + wc + 8 * j + g];
                mma_tf32(acc[0][j], a[0][0], a[0][1], a[0][2], a[0][3], b0, b1);
                mma_tf32(acc[1][j], a[1][0], a[1][1], a[1][2], a[1][3], b0, b1);
            }
        }
    }

    // epilogue
    const bool pack = (blockIdx.y == 1) && pack_b;
    uint8_t* pf = (uint8_t*)g_pf;
#pragma unroll
    for (int mt = 0; mt < 2; mt++) {
#pragma unroll
        for (int j = 0; j < 8; j++) {
            int col = wc + 8 * j + 2 * tg;
            int r0 = m0 + wr + 16 * mt + g;
            int r1 = r0 + 8;
            if (pack) {
                size_t o0 = (size_t)r0 * 512 + (col >> 2) * 16 + (col & 3) * 2;
                size_t o1 = (size_t)r1 * 512 + (col >> 2) * 16 + (col & 3) * 2;
                if (r0 < M)
                    *(__half2*)(pf + o0) = __floats2half2_rn(acc[mt][j][0], acc[mt][j][1]);
                if (r1 < M)
                    *(__half2*)(pf + o1) = __floats2half2_rn(acc[mt][j][2], acc[mt][j][3]);
            } else {
                float bv0 = bias_a ? bias_a[col]     : 0.f;
                float bv1 = bias_a ? bias_a[col + 1] : 0.f;
                if (r0 < M) {
                    float2 v = {acc[mt][j][0] + bv0, acc[mt][j][1] + bv1};
                    *(float2*)(Ca + (size_t)r0 * 128 + col) = v;
                }
                if (r1 < M) {
                    float2 v = {acc[mt][j][2] + bv0, acc[mt][j][3] + bv1};
                    *(float2*)(Ca + (size_t)r1 * 128 + col) = v;
                }
            }
        }
    }
}

// ---------------------------------------------------------------------------
// rowptr by scatter: thread per edge; writes rp[n]=e for n in (dst[e-1],dst[e]].
// ---------------------------------------------------------------------------
__global__ void rowptr_kernel(const int* __restrict__ dst, int N, int E)
{
    int e = blockIdx.x * blockDim.x + threadIdx.x;
    if (e >= E) return;
    int d1 = dst[e];
    int d0 = (e == 0) ? -1 : dst[e - 1];
    for (int n = d0 + 1; n <= d1; n++) g_rp[n] = e;
    if (e == E - 1)
        for (int n = d1 + 1; n <= N; n++) g_rp[n] = E;
}

// ---------------------------------------------------------------------------
// Fused edge phase, max-free softmax. One WARP per node; lane owns feats
// 4l..4l+3. ps+feat read as ONE packed fp16 LDG.128 per edge per lane.
// ---------------------------------------------------------------------------
__global__ void __launch_bounds__(256) edge_fused_kernel(
    const int* __restrict__ src, const float* __restrict__ w2, int N)
{
    const int gw   = (blockIdx.x * blockDim.x + threadIdx.x) >> 5;
    const int lane = threadIdx.x & 31;
    if (gw >= N) return;
    const int node = gw;
    const int r0 = g_rp[node], r1 = g_rp[node + 1];

    const float4 pdv = ((const float4*)(g_pd + (size_t)node * F))[lane];
    const float4 wv  = ((const float4*)w2)[lane];

    float4 acc = {0.f, 0.f, 0.f, 0.f};
    float  den = 0.f;

    int e = r0;
    for (; e + 2 <= r1; e += 2) {
        int s0 = __ldg(src + e);
        int s1 = __ldg(src + e + 1);
        uint4 v0 = g_pf[(size_t)s0 * 32 + lane];
        uint4 v1 = g_pf[(size_t)s1 * 32 + lane];
        float2 p0a = unp_h2(v0.x), p0b = unp_h2(v0.y);
        float2 f0a = unp_h2(v0.z), f0b = unp_h2(v0.w);
        float2 p1a = unp_h2(v1.x), p1b = unp_h2(v1.y);
        float2 f1a = unp_h2(v1.z), f1b = unp_h2(v1.w);

        float sc0 = wv.x * tanh_fast(pdv.x + p0a.x) + wv.y * tanh_fast(pdv.y + p0a.y)
                  + wv.z * tanh_fast(pdv.z + p0b.x) + wv.w * tanh_fast(pdv.w + p0b.y);
        float sc1 = wv.x * tanh_fast(pdv.x + p1a.x) + wv.y * tanh_fast(pdv.y + p1a.y)
                  + wv.z * tanh_fast(pdv.z + p1b.x) + wv.w * tanh_fast(pdv.w + p1b.y);
#pragma unroll
        for (int o = 16; o; o >>= 1) {
            sc0 += __shfl_xor_sync(0xffffffffu, sc0, o);
            sc1 += __shfl_xor_sync(0xffffffffu, sc1, o);
        }
        float ex0 = __expf(sc0);
        float ex1 = __expf(sc1);
        den += ex0 + ex1;
        acc.x = fmaf(ex0, f0a.x, acc.x); acc.x = fmaf(ex1, f1a.x, acc.x);
        acc.y = fmaf(ex0, f0a.y, acc.y); acc.y = fmaf(ex1, f1a.y, acc.y);
        acc.z = fmaf(ex0, f0b.x, acc.z); acc.z = fmaf(ex1, f1b.x, acc.z);
        acc.w = fmaf(ex0, f0b.y, acc.w); acc.w = fmaf(ex1, f1b.y, acc.w);
    }
    if (e < r1) {
        int s0 = __ldg(src + e);
        uint4 v0 = g_pf[(size_t)s0 * 32 + lane];
        float2 p0a = unp_h2(v0.x), p0b = unp_h2(v0.y);
        float2 f0a = unp_h2(v0.z), f0b = unp_h2(v0.w);
        float sc0 = wv.x * tanh_fast(pdv.x + p0a.x) + wv.y * tanh_fast(pdv.y + p0a.y)
                  + wv.z * tanh_fast(pdv.z + p0b.x) + wv.w * tanh_fast(pdv.w + p0b.y);
#pragma unroll
        for (int o = 16; o; o >>= 1) sc0 += __shfl_xor_sync(0xffffffffu, sc0, o);
        float ex0 = __expf(sc0);
        den += ex0;
        acc.x = fmaf(ex0, f0a.x, acc.x);
        acc.y = fmaf(ex0, f0a.y, acc.y);
        acc.z = fmaf(ex0, f0b.x, acc.z);
        acc.w = fmaf(ex0, f0b.y, acc.w);
    }

    const float inv = (r1 > r0) ? (1.0f / den) : 0.f;
    uint4 o = {f2tf(acc.x * inv), f2tf(acc.y * inv),
               f2tf(acc.z * inv), f2tf(acc.w * inv)};
    ((uint4*)(g_nt + (size_t)node * F))[lane] = o;
}

// ---------------------------------------------------------------------------
extern "C" void kernel_launch(void* const* d_in, const int* in_sizes, int n_in,
                              void* d_out, int out_size)
{
    const float* feat = (const float*)d_in[0];
    const int*   src  = (const int*)d_in[1];
    const int*   dst  = (const int*)d_in[2];
    const float* w1   = (const float*)d_in[3];
    const float* b1   = (const float*)d_in[4];
    const float* w2   = (const float*)d_in[5];
    // d_in[6] = b2: cancels in softmax, unused
    const float* wf   = (const float*)d_in[7];
    const float* bf   = (const float*)d_in[8];
    float* out = (float*)d_out;

    const int N = in_sizes[0] / F;   // 40000
    const int E = in_sizes[1];       // 640000

    static int init_done = 0;
    static cudaStream_t s_side;
    static cudaEvent_t ev_fork, ev_side;
    if (!init_done) {
        cudaFuncSetAttribute(gemm_tf32,
            cudaFuncAttributeMaxDynamicSharedMemorySize, GEMM_SMEM);
        cudaStreamCreateWithFlags(&s_side, cudaStreamNonBlocking);
        cudaEventCreateWithFlags(&ev_fork, cudaEventDisableTiming);
        cudaEventCreateWithFlags(&ev_side, cudaEventDisableTiming);
        init_done = 1;
    }

    float *pd;
    uint32_t *nt;
    cudaGetSymbolAddress((void**)&pd, g_pd);
    cudaGetSymbolAddress((void**)&nt, g_nt);

    // raw fp32 bits = valid truncated-tf32 operands for A AND B
    const uint32_t* fe32 = (const uint32_t*)feat;
    const uint32_t* w1b  = (const uint32_t*)w1;
    const uint32_t* wfb  = (const uint32_t*)wf;
    const int gblocks = (N + 127) / 128;            // 313

    // ---- side stream: rowptr + packed-fp16 feat halves (hide under GEMM1) ----
    cudaEventRecord(ev_fork, 0);
    cudaStreamWaitEvent(s_side, ev_fork, 0);
    rowptr_kernel<<<(E + 255) / 256, 256, 0, s_side>>>(dst, N, E);
    conv_pf<<<(N * F / 4 + 255) / 256, 256, 0, s_side>>>(feat, N * F / 4);
    cudaEventRecord(ev_side, s_side);

    // ---- main stream: 3 launches ----
    // 1) fused pair: y=0: pd = feat @ w1[:F] + b1 (fp32)
    //                y=1: ps = feat @ w1[F:]  -> packed fp16 into g_pf
    gemm_tf32<<<dim3(gblocks, 2), 256, GEMM_SMEM>>>(
        fe32, w1b, w1b + F * F, NULL, NULL, b1, pd, 1, N);

    // 2) edge phase (needs rowptr + g_pf feat halves from side, pd/ps from GEMM1)
    cudaStreamWaitEvent(0, ev_side, 0);
    edge_fused_kernel<<<(N * 32 + 255) / 256, 256>>>(src, w2, N);

    // 3) out = feat @ wf[:F] + neigh @ wf[F:] + bf  (dual-source GEMM)
    gemm_tf32<<<dim3(gblocks, 1), 256, GEMM_SMEM>>>(
        fe32, wfb, NULL, nt, wfb + F * F, bf, out, 0, N);
}